// round 2
// baseline (speedup 1.0000x reference)
#include <cuda_runtime.h>
#include <math.h>

#define NBLK 512
#define BS   256
#define KHN  8
#define DH   128
#define BN   32
#define HN   32
#define MBN  16
#define REP  4
#define QK_SCALE 0.08838834764831845f

// Split-KV partial results: per (b, kv_head, chunk, rep_head)
__device__ float  g_part_acc[BN * KHN * MBN * REP * DH];   // 8 MB
__device__ float2 g_part_ml [BN * KHN * MBN * REP];        // 128 KB

__global__ void __launch_bounds__(256)
attn_partial_kernel(const float* __restrict__ q,
                    const float* __restrict__ knew,
                    const float* __restrict__ vnew,
                    const float* __restrict__ kc,
                    const float* __restrict__ vc,
                    const int*   __restrict__ bt,
                    const int*   __restrict__ cl)
{
    const int c = blockIdx.x;   // chunk (cache block index within sequence)
    const int g = blockIdx.y;   // kv head
    const int b = blockIdx.z;   // sequence

    const int len   = cl[b];
    const int start = c * BS;
    if (start >= len) return;                    // inactive chunk
    const int n    = min(BS, len - start);       // valid tokens in this chunk
    const int last = len - 1;
    const int tsub = ((last >> 8) == c) ? (last & (BS - 1)) : -1;  // new-token slot
    const int blk  = bt[b * MBN + c];

    __shared__ float qs[REP * DH];       // 2 KB: 4 query heads
    __shared__ float sc[REP][BS];        // 4 KB: scores -> probabilities
    __shared__ float accs[REP * DH];     // 2 KB: half-CTA partial acc

    const int tid = threadIdx.x;

    // ---- load Q (heads g*4 .. g*4+3 are contiguous in q) ----
    {
        const size_t qoff = (size_t)b * HN * DH + (size_t)g * REP * DH;
        qs[tid]       = q[qoff + tid];
        qs[tid + 256] = q[qoff + tid + 256];
    }
    __syncthreads();

    const int w    = tid >> 5;
    const int lane = tid & 31;
    const int sub  = lane & 7;     // 8 lanes cooperate per token row
    const int grp  = lane >> 3;    // 4 tokens in flight per warp pass

    const size_t rowstride = (size_t)KHN * DH;   // floats between tokens
    const float* kbase = kc + ((size_t)blk * BS * KHN + (size_t)g) * DH;
    const float* knrow = knew + (size_t)(b * KHN + g) * DH;
    const float4* q4   = (const float4*)qs;

    // ---- phase 1: scores = (Q . K) * scale ----
    #pragma unroll
    for (int p = 0; p < 8; ++p) {
        const int t = w * 32 + p * 4 + grp;       // 0..255, all covered
        float s0 = 0.f, s1 = 0.f, s2 = 0.f, s3 = 0.f;
        if (t < n) {
            const float4* kr = (const float4*)((t == tsub)
                                 ? knrow
                                 : (kbase + (size_t)t * rowstride));
            #pragma unroll
            for (int j = 0; j < 4; ++j) {
                const float4 kv = kr[sub * 4 + j];
                float4 qa;
                qa = q4[      sub * 4 + j];
                s0 += kv.x*qa.x + kv.y*qa.y + kv.z*qa.z + kv.w*qa.w;
                qa = q4[32  + sub * 4 + j];
                s1 += kv.x*qa.x + kv.y*qa.y + kv.z*qa.z + kv.w*qa.w;
                qa = q4[64  + sub * 4 + j];
                s2 += kv.x*qa.x + kv.y*qa.y + kv.z*qa.z + kv.w*qa.w;
                qa = q4[96  + sub * 4 + j];
                s3 += kv.x*qa.x + kv.y*qa.y + kv.z*qa.z + kv.w*qa.w;
            }
        }
        // reduce across the 8-lane group (xor 4,2,1 stays inside the group)
        #pragma unroll
        for (int m = 4; m > 0; m >>= 1) {
            s0 += __shfl_xor_sync(0xffffffffu, s0, m);
            s1 += __shfl_xor_sync(0xffffffffu, s1, m);
            s2 += __shfl_xor_sync(0xffffffffu, s2, m);
            s3 += __shfl_xor_sync(0xffffffffu, s3, m);
        }
        if (sub < 4) {
            const float val = (sub == 0) ? s0 : (sub == 1) ? s1 : (sub == 2) ? s2 : s3;
            sc[sub][t] = (t < n) ? val * QK_SCALE : -INFINITY;
        }
    }
    __syncthreads();

    // ---- phase 2: per-head chunk softmax (unnormalized), warp r handles head r ----
    const int mlbase = ((b * KHN + g) * MBN + c) * REP;
    if (w < 4) {
        float vv[8];
        float m = -INFINITY;
        #pragma unroll
        for (int j = 0; j < 8; ++j) {
            vv[j] = sc[w][lane + 32 * j];
            m = fmaxf(m, vv[j]);
        }
        #pragma unroll
        for (int s = 16; s > 0; s >>= 1)
            m = fmaxf(m, __shfl_xor_sync(0xffffffffu, m, s));
        float l = 0.f;
        #pragma unroll
        for (int j = 0; j < 8; ++j) {
            const float e = __expf(vv[j] - m);   // exp(-inf)=0 for masked slots
            l += e;
            sc[w][lane + 32 * j] = e;
        }
        #pragma unroll
        for (int s = 16; s > 0; s >>= 1)
            l += __shfl_xor_sync(0xffffffffu, l, s);
        if (lane == 0)
            g_part_ml[mlbase + w] = make_float2(m, l);
    }
    __syncthreads();

    // ---- phase 3: acc = P . V  (thread d owns dim d; two halves over tokens) ----
    const int d    = tid & 127;
    const int half = tid >> 7;
    const float* vbase = vc + ((size_t)blk * BS * KHN + (size_t)g) * DH + d;
    const float  vnv   = vnew[(size_t)(b * KHN + g) * DH + d];

    float a0 = 0.f, a1 = 0.f, a2 = 0.f, a3 = 0.f;
    const int t0 = half * 128;
    const int t1 = min(t0 + 128, n);
    #pragma unroll 8
    for (int t = t0; t < t1; ++t) {
        const float vv = (t == tsub) ? vnv : vbase[(size_t)t * rowstride];
        a0 = fmaf(sc[0][t], vv, a0);
        a1 = fmaf(sc[1][t], vv, a1);
        a2 = fmaf(sc[2][t], vv, a2);
        a3 = fmaf(sc[3][t], vv, a3);
    }

    if (half == 0) {
        accs[d]       = a0;
        accs[128 + d] = a1;
        accs[256 + d] = a2;
        accs[384 + d] = a3;
    }
    __syncthreads();
    if (half == 1) {
        float* o = g_part_acc + (size_t)mlbase * DH + d;
        o[0]        = a0 + accs[d];
        o[DH]       = a1 + accs[128 + d];
        o[2 * DH]   = a2 + accs[256 + d];
        o[3 * DH]   = a3 + accs[384 + d];
    }
}

// ---- log-sum-exp combine across chunks ----
__global__ void __launch_bounds__(512)
attn_combine_kernel(const int* __restrict__ cl, float* __restrict__ out)
{
    const int g = blockIdx.x;
    const int b = blockIdx.y;
    const int len = cl[b];
    const int nc  = (len + BS - 1) >> 8;

    const int tid = threadIdx.x;
    const int r   = tid >> 7;
    const int d   = tid & 127;
    const int base = (b * KHN + g) * MBN;

    float M = -INFINITY;
    for (int c = 0; c < nc; ++c)
        M = fmaxf(M, g_part_ml[(base + c) * REP + r].x);

    float L = 0.f, o = 0.f;
    for (int c = 0; c < nc; ++c) {
        const float2 ml = g_part_ml[(base + c) * REP + r];
        const float wgt = __expf(ml.x - M);
        L += ml.y * wgt;
        o += wgt * g_part_acc[((size_t)(base + c) * REP + r) * DH + d];
    }
    out[(size_t)b * HN * DH + (size_t)(g * REP + r) * DH + d] = o / L;
}

extern "C" void kernel_launch(void* const* d_in, const int* in_sizes, int n_in,
                              void* d_out, int out_size)
{
    const float* q  = (const float*)d_in[0];
    const float* k  = (const float*)d_in[1];
    const float* v  = (const float*)d_in[2];
    const float* kc = (const float*)d_in[3];
    const float* vc = (const float*)d_in[4];
    const int*   bt = (const int*)d_in[5];
    const int*   cl = (const int*)d_in[6];
    // d_in[7] = slot_mapping: unused — new token is substituted at position len-1
    float* out = (float*)d_out;

    dim3 grid1(MBN, KHN, BN);       // chunk x kv_head x batch
    attn_partial_kernel<<<grid1, 256>>>(q, k, v, kc, vc, bt, cl);

    dim3 grid2(KHN, BN);
    attn_combine_kernel<<<grid2, 512>>>(cl, out);
}

// round 3
// speedup vs baseline: 1.0928x; 1.0928x over previous
#include <cuda_runtime.h>
#include <math.h>

#define NBLK 512
#define BS   256
#define KHN  8
#define DH   128
#define BN   32
#define HN   32
#define MBN  16
#define REP  4
#define QK_SCALE 0.08838834764831845f

// Split-KV partial results: per (b, kv_head, chunk, rep_head)
__device__ float  g_part_acc[BN * KHN * MBN * REP * DH];   // 8 MB
__device__ float2 g_part_ml [BN * KHN * MBN * REP];        // 128 KB

__global__ void __launch_bounds__(256, 4)
attn_partial_kernel(const float* __restrict__ q,
                    const float* __restrict__ knew,
                    const float* __restrict__ vnew,
                    const float* __restrict__ kc,
                    const float* __restrict__ vc,
                    const int*   __restrict__ bt,
                    const int*   __restrict__ cl)
{
    const int c = blockIdx.x;   // chunk (cache block index within sequence)
    const int g = blockIdx.y;   // kv head
    const int b = blockIdx.z;   // sequence

    const int len   = cl[b];
    const int start = c * BS;
    if (start >= len) return;                    // inactive chunk
    const int n    = min(BS, len - start);       // valid tokens in this chunk
    const int last = len - 1;
    const int tsub = ((last >> 8) == c) ? (last & (BS - 1)) : -1;  // new-token slot
    const int blk  = bt[b * MBN + c];

    __shared__ float qs[REP * DH];       // 2 KB: 4 query heads
    __shared__ float sc[REP][BS];        // 4 KB: scores -> probabilities
    __shared__ float red[8 * REP * DH];  // 16 KB: per-warp V partials

    const int tid = threadIdx.x;

    // ---- load Q (heads g*4 .. g*4+3 are contiguous in q) ----
    {
        const size_t qoff = (size_t)b * HN * DH + (size_t)g * REP * DH;
        qs[tid]       = q[qoff + tid];
        qs[tid + 256] = q[qoff + tid + 256];
    }
    __syncthreads();

    const int w    = tid >> 5;
    const int lane = tid & 31;
    const int sub  = lane & 7;     // 8 lanes cooperate per token row
    const int grp  = lane >> 3;    // 4 tokens in flight per warp pass

    const size_t rowstride = (size_t)KHN * DH;   // floats between tokens
    const float* kbase = kc + ((size_t)blk * BS * KHN + (size_t)g) * DH;
    const float* knrow = knew + (size_t)(b * KHN + g) * DH;
    const float4* q4   = (const float4*)qs;

    // ---- phase 1: scores = (Q . K) * scale ----
    #pragma unroll 2
    for (int p = 0; p < 8; ++p) {
        const int t = w * 32 + p * 4 + grp;       // 0..255, all covered
        float s0 = 0.f, s1 = 0.f, s2 = 0.f, s3 = 0.f;
        if (t < n) {
            const float4* kr = (const float4*)((t == tsub)
                                 ? knrow
                                 : (kbase + (size_t)t * rowstride));
            #pragma unroll
            for (int j = 0; j < 4; ++j) {
                const float4 kv = kr[sub * 4 + j];
                float4 qa;
                qa = q4[      sub * 4 + j];
                s0 += kv.x*qa.x + kv.y*qa.y + kv.z*qa.z + kv.w*qa.w;
                qa = q4[32  + sub * 4 + j];
                s1 += kv.x*qa.x + kv.y*qa.y + kv.z*qa.z + kv.w*qa.w;
                qa = q4[64  + sub * 4 + j];
                s2 += kv.x*qa.x + kv.y*qa.y + kv.z*qa.z + kv.w*qa.w;
                qa = q4[96  + sub * 4 + j];
                s3 += kv.x*qa.x + kv.y*qa.y + kv.z*qa.z + kv.w*qa.w;
            }
        }
        // reduce across the 8-lane group (xor 4,2,1 stays inside the group)
        #pragma unroll
        for (int m = 4; m > 0; m >>= 1) {
            s0 += __shfl_xor_sync(0xffffffffu, s0, m);
            s1 += __shfl_xor_sync(0xffffffffu, s1, m);
            s2 += __shfl_xor_sync(0xffffffffu, s2, m);
            s3 += __shfl_xor_sync(0xffffffffu, s3, m);
        }
        if (sub < 4) {
            const float val = (sub == 0) ? s0 : (sub == 1) ? s1 : (sub == 2) ? s2 : s3;
            sc[sub][t] = (t < n) ? val * QK_SCALE : -INFINITY;
        }
    }
    __syncthreads();

    // ---- phase 2: per-head chunk softmax (unnormalized), warp r handles head r ----
    const int mlbase = ((b * KHN + g) * MBN + c) * REP;
    if (w < 4) {
        float vv[8];
        float m = -INFINITY;
        #pragma unroll
        for (int j = 0; j < 8; ++j) {
            vv[j] = sc[w][lane + 32 * j];
            m = fmaxf(m, vv[j]);
        }
        #pragma unroll
        for (int s = 16; s > 0; s >>= 1)
            m = fmaxf(m, __shfl_xor_sync(0xffffffffu, m, s));
        float l = 0.f;
        #pragma unroll
        for (int j = 0; j < 8; ++j) {
            const float e = __expf(vv[j] - m);   // exp(-inf)=0 for masked slots
            l += e;
            sc[w][lane + 32 * j] = e;
        }
        #pragma unroll
        for (int s = 16; s > 0; s >>= 1)
            l += __shfl_xor_sync(0xffffffffu, l, s);
        if (lane == 0)
            g_part_ml[mlbase + w] = make_float2(m, l);
    }
    __syncthreads();

    // ---- phase 3: acc = P . V  (warp per token row; lane owns float4 of dims) ----
    // Warp w handles tokens w, w+8, w+16, ... Lane reads V[t][lane*4 .. lane*4+3].
    {
        const int lo = lane * 4;   // float offset within the 128-dim row
        const float* vrow0 = vc + ((size_t)blk * BS * KHN + (size_t)g) * DH + lo;
        const float4 vn4 = *(const float4*)(vnew + (size_t)(b * KHN + g) * DH + lo);

        float4 a0 = make_float4(0.f, 0.f, 0.f, 0.f);
        float4 a1 = a0, a2 = a0, a3 = a0;

        #pragma unroll 4
        for (int t = w; t < n; t += 8) {
            const float4 vv = (t == tsub) ? vn4
                              : *(const float4*)(vrow0 + (size_t)t * rowstride);
            const float p0 = sc[0][t];
            const float p1 = sc[1][t];
            const float p2 = sc[2][t];
            const float p3 = sc[3][t];
            a0.x = fmaf(p0, vv.x, a0.x); a0.y = fmaf(p0, vv.y, a0.y);
            a0.z = fmaf(p0, vv.z, a0.z); a0.w = fmaf(p0, vv.w, a0.w);
            a1.x = fmaf(p1, vv.x, a1.x); a1.y = fmaf(p1, vv.y, a1.y);
            a1.z = fmaf(p1, vv.z, a1.z); a1.w = fmaf(p1, vv.w, a1.w);
            a2.x = fmaf(p2, vv.x, a2.x); a2.y = fmaf(p2, vv.y, a2.y);
            a2.z = fmaf(p2, vv.z, a2.z); a2.w = fmaf(p2, vv.w, a2.w);
            a3.x = fmaf(p3, vv.x, a3.x); a3.y = fmaf(p3, vv.y, a3.y);
            a3.z = fmaf(p3, vv.z, a3.z); a3.w = fmaf(p3, vv.w, a3.w);
        }

        // per-warp partials to smem: red[w][h*128 + lane*4 .. +3]
        float* rw = red + w * (REP * DH);
        *(float4*)(rw + 0 * DH + lo) = a0;
        *(float4*)(rw + 1 * DH + lo) = a1;
        *(float4*)(rw + 2 * DH + lo) = a2;
        *(float4*)(rw + 3 * DH + lo) = a3;
    }
    __syncthreads();

    // ---- reduce 8 warps and write partial result ----
    {
        float* gout = g_part_acc + (size_t)mlbase * DH;
        #pragma unroll
        for (int o = tid; o < REP * DH; o += 256) {
            float s = 0.f;
            #pragma unroll
            for (int ww = 0; ww < 8; ++ww)
                s += red[ww * (REP * DH) + o];
            gout[o] = s;
        }
    }
}

// ---- log-sum-exp combine across chunks ----
__global__ void __launch_bounds__(512)
attn_combine_kernel(const int* __restrict__ cl, float* __restrict__ out)
{
    const int g = blockIdx.x;
    const int b = blockIdx.y;
    const int len = cl[b];
    const int nc  = (len + BS - 1) >> 8;

    const int tid = threadIdx.x;
    const int r   = tid >> 7;
    const int d   = tid & 127;
    const int base = (b * KHN + g) * MBN;

    float M = -INFINITY;
    for (int c = 0; c < nc; ++c)
        M = fmaxf(M, g_part_ml[(base + c) * REP + r].x);

    float L = 0.f, o = 0.f;
    for (int c = 0; c < nc; ++c) {
        const float2 ml = g_part_ml[(base + c) * REP + r];
        const float wgt = __expf(ml.x - M);
        L += ml.y * wgt;
        o += wgt * g_part_acc[((size_t)(base + c) * REP + r) * DH + d];
    }
    out[(size_t)b * HN * DH + (size_t)(g * REP + r) * DH + d] = o / L;
}

extern "C" void kernel_launch(void* const* d_in, const int* in_sizes, int n_in,
                              void* d_out, int out_size)
{
    const float* q  = (const float*)d_in[0];
    const float* k  = (const float*)d_in[1];
    const float* v  = (const float*)d_in[2];
    const float* kc = (const float*)d_in[3];
    const float* vc = (const float*)d_in[4];
    const int*   bt = (const int*)d_in[5];
    const int*   cl = (const int*)d_in[6];
    // d_in[7] = slot_mapping: unused — new token is substituted at position len-1
    float* out = (float*)d_out;

    dim3 grid1(MBN, KHN, BN);       // chunk x kv_head x batch
    attn_partial_kernel<<<grid1, 256>>>(q, k, v, kc, vc, bt, cl);

    dim3 grid2(KHN, BN);
    attn_combine_kernel<<<grid2, 512>>>(cl, out);
}

// round 6
// speedup vs baseline: 1.9613x; 1.7947x over previous
#include <cuda_runtime.h>
#include <math.h>

#define NBLK 512
#define BS   256
#define KHN  8
#define DH   128
#define BN   32
#define HN   32
#define MBN  16
#define REP  4
#define QK_SCALE 0.08838834764831845f

// Split-KV partial results: per (b, kv_head, chunk, rep_head)
__device__ float  g_part_acc[BN * KHN * MBN * REP * DH];   // 8 MB
__device__ float2 g_part_ml [BN * KHN * MBN * REP];        // 128 KB

// Alignment marker so ncu -s 5 -c 1 lands on attn_partial_kernel
// (4 launches per call -> 6th launch overall is the partial kernel).
__global__ void noop_kernel() {}

__global__ void __launch_bounds__(256, 4)
attn_partial_kernel(const float* __restrict__ q,
                    const float* __restrict__ knew,
                    const float* __restrict__ vnew,
                    const float* __restrict__ kc,
                    const float* __restrict__ vc,
                    const int*   __restrict__ bt,
                    const int*   __restrict__ cl)
{
    const int c = blockIdx.x;   // chunk (cache block index within sequence)
    const int g = blockIdx.y;   // kv head
    const int b = blockIdx.z;   // sequence

    const int len   = cl[b];
    const int start = c * BS;
    if (start >= len) return;                    // inactive chunk
    const int n    = min(BS, len - start);       // valid tokens in this chunk
    const int last = len - 1;
    const int tsub = ((last >> 8) == c) ? (last & (BS - 1)) : -1;  // new-token slot
    const int blk  = bt[b * MBN + c];

    __shared__ float qs[REP * DH];       // 2 KB: 4 query heads
    __shared__ float sc[REP][BS];        // 4 KB: scores -> probabilities
    __shared__ float red[8 * REP * DH];  // 16 KB: per-warp V partials

    const int tid = threadIdx.x;

    // ---- load Q (heads g*4 .. g*4+3 are contiguous in q) ----
    {
        const size_t qoff = (size_t)b * HN * DH + (size_t)g * REP * DH;
        qs[tid]       = q[qoff + tid];
        qs[tid + 256] = q[qoff + tid + 256];
    }
    __syncthreads();

    const int w    = tid >> 5;
    const int lane = tid & 31;
    const int sub  = lane & 7;     // 8 lanes cooperate per token row
    const int grp  = lane >> 3;    // 4 tokens in flight per warp pass

    const size_t rowstride = (size_t)KHN * DH;   // floats between tokens
    const float* kbase = kc + ((size_t)blk * BS * KHN + (size_t)g) * DH;
    const float* knrow = knew + (size_t)(b * KHN + g) * DH;
    const float4* q4   = (const float4*)qs;

    // ---- phase 1: scores = (Q . K) * scale ----
    // Lane group of 8 reads CONTIGUOUS 128B per j-step (1 cache line per row
    // per instruction instead of 4): kr[j*8 + sub].
    #pragma unroll 2
    for (int p = 0; p < 8; ++p) {
        const int t = w * 32 + p * 4 + grp;       // 0..255, all covered
        float s0 = 0.f, s1 = 0.f, s2 = 0.f, s3 = 0.f;
        if (t < n) {
            const float4* kr = (const float4*)((t == tsub)
                                 ? knrow
                                 : (kbase + (size_t)t * rowstride));
            #pragma unroll
            for (int j = 0; j < 4; ++j) {
                const float4 kv = kr[j * 8 + sub];
                float4 qa;
                qa = q4[      j * 8 + sub];
                s0 += kv.x*qa.x + kv.y*qa.y + kv.z*qa.z + kv.w*qa.w;
                qa = q4[32  + j * 8 + sub];
                s1 += kv.x*qa.x + kv.y*qa.y + kv.z*qa.z + kv.w*qa.w;
                qa = q4[64  + j * 8 + sub];
                s2 += kv.x*qa.x + kv.y*qa.y + kv.z*qa.z + kv.w*qa.w;
                qa = q4[96  + j * 8 + sub];
                s3 += kv.x*qa.x + kv.y*qa.y + kv.z*qa.z + kv.w*qa.w;
            }
        }
        // reduce across the 8-lane group (xor 4,2,1 stays inside the group)
        #pragma unroll
        for (int m = 4; m > 0; m >>= 1) {
            s0 += __shfl_xor_sync(0xffffffffu, s0, m);
            s1 += __shfl_xor_sync(0xffffffffu, s1, m);
            s2 += __shfl_xor_sync(0xffffffffu, s2, m);
            s3 += __shfl_xor_sync(0xffffffffu, s3, m);
        }
        if (sub < 4) {
            const float val = (sub == 0) ? s0 : (sub == 1) ? s1 : (sub == 2) ? s2 : s3;
            sc[sub][t] = (t < n) ? val * QK_SCALE : -INFINITY;
        }
    }
    __syncthreads();

    // ---- phase 2: per-head chunk softmax (unnormalized), warp r handles head r ----
    const int mlbase = ((b * KHN + g) * MBN + c) * REP;
    if (w < 4) {
        float vv[8];
        float m = -INFINITY;
        #pragma unroll
        for (int j = 0; j < 8; ++j) {
            vv[j] = sc[w][lane + 32 * j];
            m = fmaxf(m, vv[j]);
        }
        #pragma unroll
        for (int s = 16; s > 0; s >>= 1)
            m = fmaxf(m, __shfl_xor_sync(0xffffffffu, m, s));
        float l = 0.f;
        #pragma unroll
        for (int j = 0; j < 8; ++j) {
            const float e = __expf(vv[j] - m);   // exp(-inf)=0 for masked slots
            l += e;
            sc[w][lane + 32 * j] = e;
        }
        #pragma unroll
        for (int s = 16; s > 0; s >>= 1)
            l += __shfl_xor_sync(0xffffffffu, l, s);
        if (lane == 0)
            g_part_ml[mlbase + w] = make_float2(m, l);
    }
    __syncthreads();

    // ---- phase 3: acc = P . V  (warp per token row; lane owns float4 of dims) ----
    {
        const int lo = lane * 4;   // float offset within the 128-dim row
        const float* vrow0 = vc + ((size_t)blk * BS * KHN + (size_t)g) * DH + lo;
        const float4 vn4 = *(const float4*)(vnew + (size_t)(b * KHN + g) * DH + lo);

        float4 a0 = make_float4(0.f, 0.f, 0.f, 0.f);
        float4 a1 = a0, a2 = a0, a3 = a0;

        #pragma unroll 4
        for (int t = w; t < n; t += 8) {
            const float4 vv = (t == tsub) ? vn4
                              : *(const float4*)(vrow0 + (size_t)t * rowstride);
            const float p0 = sc[0][t];
            const float p1 = sc[1][t];
            const float p2 = sc[2][t];
            const float p3 = sc[3][t];
            a0.x = fmaf(p0, vv.x, a0.x); a0.y = fmaf(p0, vv.y, a0.y);
            a0.z = fmaf(p0, vv.z, a0.z); a0.w = fmaf(p0, vv.w, a0.w);
            a1.x = fmaf(p1, vv.x, a1.x); a1.y = fmaf(p1, vv.y, a1.y);
            a1.z = fmaf(p1, vv.z, a1.z); a1.w = fmaf(p1, vv.w, a1.w);
            a2.x = fmaf(p2, vv.x, a2.x); a2.y = fmaf(p2, vv.y, a2.y);
            a2.z = fmaf(p2, vv.z, a2.z); a2.w = fmaf(p2, vv.w, a2.w);
            a3.x = fmaf(p3, vv.x, a3.x); a3.y = fmaf(p3, vv.y, a3.y);
            a3.z = fmaf(p3, vv.z, a3.z); a3.w = fmaf(p3, vv.w, a3.w);
        }

        // per-warp partials to smem: red[w][h*128 + lane*4 .. +3]
        float* rw = red + w * (REP * DH);
        *(float4*)(rw + 0 * DH + lo) = a0;
        *(float4*)(rw + 1 * DH + lo) = a1;
        *(float4*)(rw + 2 * DH + lo) = a2;
        *(float4*)(rw + 3 * DH + lo) = a3;
    }
    __syncthreads();

    // ---- reduce 8 warps and write partial result ----
    {
        float* gout = g_part_acc + (size_t)mlbase * DH;
        #pragma unroll
        for (int o = tid; o < REP * DH; o += 256) {
            float s = 0.f;
            #pragma unroll
            for (int ww = 0; ww < 8; ++ww)
                s += red[ww * (REP * DH) + o];
            gout[o] = s;
        }
    }
}

// ---- log-sum-exp combine across chunks ----
__global__ void __launch_bounds__(512)
attn_combine_kernel(const int* __restrict__ cl, float* __restrict__ out)
{
    const int g = blockIdx.x;
    const int b = blockIdx.y;
    const int len = cl[b];
    const int nc  = (len + BS - 1) >> 8;

    const int tid = threadIdx.x;
    const int r   = tid >> 7;
    const int d   = tid & 127;
    const int base = (b * KHN + g) * MBN;

    float M = -INFINITY;
    for (int c = 0; c < nc; ++c)
        M = fmaxf(M, g_part_ml[(base + c) * REP + r].x);

    float L = 0.f, o = 0.f;
    for (int c = 0; c < nc; ++c) {
        const float2 ml = g_part_ml[(base + c) * REP + r];
        const float wgt = __expf(ml.x - M);
        L += ml.y * wgt;
        o += wgt * g_part_acc[((size_t)(base + c) * REP + r) * DH + d];
    }
    out[(size_t)b * HN * DH + (size_t)(g * REP + r) * DH + d] = o / L;
}

extern "C" void kernel_launch(void* const* d_in, const int* in_sizes, int n_in,
                              void* d_out, int out_size)
{
    const float* q  = (const float*)d_in[0];
    const float* k  = (const float*)d_in[1];
    const float* v  = (const float*)d_in[2];
    const float* kc = (const float*)d_in[3];
    const float* vc = (const float*)d_in[4];
    const int*   bt = (const int*)d_in[5];
    const int*   cl = (const int*)d_in[6];
    // d_in[7] = slot_mapping: unused — new token is substituted at position len-1
    float* out = (float*)d_out;

    // 4 launches per call so ncu (-s 5 -c 1) profiles attn_partial_kernel.
    noop_kernel<<<1, 32>>>();

    dim3 grid1(MBN, KHN, BN);       // chunk x kv_head x batch
    attn_partial_kernel<<<grid1, 256>>>(q, k, v, kc, vc, bt, cl);

    dim3 grid2(KHN, BN);
    attn_combine_kernel<<<grid2, 512>>>(cl, out);

    noop_kernel<<<1, 32>>>();
}